// round 3
// baseline (speedup 1.0000x reference)
#include <cuda_runtime.h>
#include <cuda_fp16.h>
#include <cuda_bf16.h>
#include <math.h>
#include <stdint.h>

// Problem constants
#define BB 16
#define TT 512
#define DD 512
#define HH 256
#define G4H 1024
#define SCALE_C 0.1f

// ---------------------------------------------------------------------------
// Device scratch (static — no runtime allocation allowed)
// ---------------------------------------------------------------------------
__device__ float  g_xg1[(size_t)BB * TT * G4H];          // 33.5 MB
__device__ float  g_xg2[(size_t)BB * TT * G4H];          // 33.5 MB
__device__ float  g_h1 [(size_t)BB * TT * HH];           // 8.4 MB
__device__ __half g_h1h[(size_t)BB * TT * HH];           // 4.2 MB
__device__ __half g_Bt [(size_t)HH * HH * HH];           // 33.5 MB  Bt[o*256+k][d]
__device__ __half g_t  [(size_t)BB * TT * HH * HH];      // 1.07 GB  t[b,t,o,k]
__device__ float  g_hstate[3][BB][HH];                   // triple-buffered h
__device__ int    g_cnt1[BB];
__device__ int    g_cnt2[BB];

__device__ __forceinline__ float sigmoidf_(float x) { return 1.0f / (1.0f + expf(-x)); }

// ---------------------------------------------------------------------------
// init: zero barrier counters + h-state (runs every launch / graph replay)
// ---------------------------------------------------------------------------
__global__ void init_kernel() {
    int i = blockIdx.x * blockDim.x + threadIdx.x;
    if (i < BB) { g_cnt1[i] = 0; g_cnt2[i] = 0; }
    float* hs = (float*)g_hstate;
    for (int j = i; j < 3 * BB * HH; j += gridDim.x * blockDim.x) hs[j] = 0.f;
}

__global__ void zero_h0_kernel() {
    int i = blockIdx.x * blockDim.x + threadIdx.x;
    if (i < BB * HH) ((float*)g_hstate[0])[i] = 0.f;
}

// ---------------------------------------------------------------------------
// fp32 sgemm: C[M][N] = A[M][K] @ W[N][K]^T + bias[N]
// M%128==0, N%128==0, K%8==0. 128x128 tile, 256 threads, 8x8 per thread.
// ---------------------------------------------------------------------------
__global__ void __launch_bounds__(256) sgemm_nt(const float* __restrict__ A,
                                                const float* __restrict__ W,
                                                const float* __restrict__ bias,
                                                float* __restrict__ C,
                                                int M, int N, int K) {
    __shared__ float As[8][128];
    __shared__ float Bs[8][128];
    const int tid = threadIdx.x;
    const int m0 = blockIdx.y * 128, n0 = blockIdx.x * 128;
    const int tx = tid & 15, ty = tid >> 4;
    const int lrow = tid >> 1, lseg = (tid & 1) * 4;

    float acc[8][8];
#pragma unroll
    for (int i = 0; i < 8; i++)
#pragma unroll
        for (int j = 0; j < 8; j++) acc[i][j] = 0.f;

    const float* Aptr = A + (size_t)(m0 + lrow) * K + lseg;
    const float* Wptr = W + (size_t)(n0 + lrow) * K + lseg;

    for (int k0 = 0; k0 < K; k0 += 8) {
        float4 av = *(const float4*)(Aptr + k0);
        float4 wv = *(const float4*)(Wptr + k0);
        __syncthreads();
        As[lseg + 0][lrow] = av.x; As[lseg + 1][lrow] = av.y;
        As[lseg + 2][lrow] = av.z; As[lseg + 3][lrow] = av.w;
        Bs[lseg + 0][lrow] = wv.x; Bs[lseg + 1][lrow] = wv.y;
        Bs[lseg + 2][lrow] = wv.z; Bs[lseg + 3][lrow] = wv.w;
        __syncthreads();
#pragma unroll
        for (int kk = 0; kk < 8; kk++) {
            float a[8], b[8];
            *(float4*)(a)     = *(const float4*)&As[kk][ty * 8];
            *(float4*)(a + 4) = *(const float4*)&As[kk][ty * 8 + 4];
            *(float4*)(b)     = *(const float4*)&Bs[kk][tx * 8];
            *(float4*)(b + 4) = *(const float4*)&Bs[kk][tx * 8 + 4];
#pragma unroll
            for (int i = 0; i < 8; i++)
#pragma unroll
                for (int j = 0; j < 8; j++) acc[i][j] += a[i] * b[j];
        }
    }

#pragma unroll
    for (int i = 0; i < 8; i++) {
        size_t r = (size_t)(m0 + ty * 8 + i) * N;
#pragma unroll
        for (int j = 0; j < 8; j += 4) {
            int nc = n0 + tx * 8 + j;
            float4 v;
            v.x = acc[i][j + 0] + bias[nc + 0];
            v.y = acc[i][j + 1] + bias[nc + 1];
            v.z = acc[i][j + 2] + bias[nc + 2];
            v.w = acc[i][j + 3] + bias[nc + 3];
            *(float4*)&C[r + nc] = v;
        }
    }
}

// ---------------------------------------------------------------------------
// Bw (o,d,k) fp32 -> Bt[o*256+k][d] fp16 (transpose d<->k per o)
// grid (k/32, d/32, o), block (32,8)
// ---------------------------------------------------------------------------
__global__ void transpose_Bw(const float* __restrict__ Bw, __half* __restrict__ Bt) {
    __shared__ float sm[32][33];
    int o = blockIdx.z, d0 = blockIdx.y * 32, k0 = blockIdx.x * 32;
    int tx = threadIdx.x, ty = threadIdx.y;
#pragma unroll
    for (int j = 0; j < 4; j++) {
        int dl = ty + j * 8;
        sm[dl][tx] = Bw[((size_t)o * HH + (d0 + dl)) * HH + (k0 + tx)];
    }
    __syncthreads();
#pragma unroll
    for (int j = 0; j < 4; j++) {
        int kl = ty + j * 8;
        Bt[((size_t)o * HH + (k0 + kl)) * HH + (d0 + tx)] = __float2half(sm[tx][kl]);
    }
}

// ---------------------------------------------------------------------------
// sLSTM recurrence. grid: 128 CTAs (b = blk/8, ci = blk%8), 512 threads.
// Each CTA owns gate rows {type*256 + ci*32 + u : type in 0..3, u in 0..31}
// (4 threads per gate, each with a 64-float U quarter-row in registers).
// ---------------------------------------------------------------------------
__global__ void __launch_bounds__(512) slstm_kernel(const float* __restrict__ xg,
                                                    const float* __restrict__ Uw,
                                                    const float* __restrict__ Ub,
                                                    const float* __restrict__ alpha,
                                                    float* __restrict__ h1,
                                                    __half* __restrict__ h1h) {
    const int blk = blockIdx.x;
    const int b = blk >> 3, ci = blk & 7;
    const int tid = threadIdx.x;
    const int gl = tid >> 2;          // local gate 0..127
    const int q  = tid & 3;           // quarter of the K=256 dot
    const int type = gl >> 5;
    const int ul = gl & 31;
    const int row = type * HH + ci * 32 + ul;

    __shared__ float h_s[HH];
    __shared__ float sg[128];

    float4 u[16];
    const float4* Up = (const float4*)(Uw + (size_t)row * HH + q * 64);
#pragma unroll
    for (int i = 0; i < 16; i++) u[i] = Up[i];
    const float ubias = Ub[row];
    float c = 0.f;
    const float al = (tid < 32) ? alpha[ci * 32 + tid] : 0.f;
    const float* xgb = xg + (size_t)b * TT * G4H;

    for (int t = 0; t < TT; t++) {
        __syncthreads();
        if (tid < HH) h_s[tid] = __ldcg(&g_hstate[t % 3][b][tid]);
        __syncthreads();

        float acc = (q == 0) ? (xgb[(size_t)t * G4H + row] + ubias) : 0.f;
        const float4* hp = (const float4*)(h_s + q * 64);
#pragma unroll
        for (int i = 0; i < 16; i++) {
            float4 hv = hp[i];
            acc += u[i].x * hv.x + u[i].y * hv.y + u[i].z * hv.z + u[i].w * hv.w;
        }
        acc += __shfl_down_sync(0xffffffffu, acc, 2, 4);
        acc += __shfl_down_sync(0xffffffffu, acc, 1, 4);
        if (q == 0) sg[gl] = acc;
        __syncthreads();

        if (tid < 32) {
            float iv = sg[tid], fv = sg[32 + tid], ov = sg[64 + tid], gv = sg[96 + tid];
            c = al * (sigmoidf_(fv) * c + sigmoidf_(iv) * tanhf(gv));
            float h = sigmoidf_(ov) * tanhf(c);
            int ug = ci * 32 + tid;
            g_hstate[(t + 1) % 3][b][ug] = h;
            size_t oi = ((size_t)b * TT + t) * HH + ug;
            h1[oi] = h;
            h1h[oi] = __float2half(h);
            __threadfence();
        }
        __syncthreads();
        if (tid == 0) {
            atomicAdd(&g_cnt1[b], 1);
            while (atomicAdd(&g_cnt1[b], 0) < 8 * (t + 1)) {}
        }
        __syncthreads();
    }
}

// ---------------------------------------------------------------------------
// hgemm: Ct[m][n] = sum_d A[m][d] * Bm[n][d], fp16 in, fp32 acc, fp16 out.
// M=8192, N=65536, K=256. 128x128 tiles, BK=32, 8 warps, cp.async 2-stage.
// ---------------------------------------------------------------------------
#define LDSM4(R0, R1, R2, R3, addr)                                              \
    asm volatile("ldmatrix.sync.aligned.m8n8.x4.shared.b16 {%0,%1,%2,%3}, [%4];" \
                 : "=r"(R0), "=r"(R1), "=r"(R2), "=r"(R3) : "r"(addr))

__global__ void __launch_bounds__(256) hgemm_kernel(const __half* __restrict__ A,
                                                    const __half* __restrict__ Bm,
                                                    __half* __restrict__ Ct) {
    const int K = HH;                 // 256
    const size_t NN = (size_t)HH * HH;  // 65536
    __shared__ __half As[2][128][40];
    __shared__ __half Bs[2][128][40];

    const int tid = threadIdx.x;
    const int wid = tid >> 5, lane = tid & 31;
    const int wm = (wid >> 2) * 64;   // 0 / 64
    const int wn = (wid & 3) * 32;    // 0..96
    const int m0 = blockIdx.y * 128;
    const int n0 = blockIdx.x * 128;

    float acc[4][4][4];
#pragma unroll
    for (int mf = 0; mf < 4; mf++)
#pragma unroll
        for (int nf = 0; nf < 4; nf++)
#pragma unroll
            for (int r = 0; r < 4; r++) acc[mf][nf][r] = 0.f;

    // stage loader: 512 16B chunks per operand per stage / 256 threads
    auto stage_load = [&](int kt, int st) {
#pragma unroll
        for (int i = 0; i < 2; i++) {
            int cidx = tid + i * 256;
            int r = cidx >> 2, seg = cidx & 3;
            unsigned da = (unsigned)__cvta_generic_to_shared(&As[st][r][seg * 8]);
            const __half* sa = A + (size_t)(m0 + r) * K + kt * 32 + seg * 8;
            asm volatile("cp.async.cg.shared.global [%0], [%1], 16;" :: "r"(da), "l"(sa));
            unsigned db = (unsigned)__cvta_generic_to_shared(&Bs[st][r][seg * 8]);
            const __half* sb = Bm + (size_t)(n0 + r) * K + kt * 32 + seg * 8;
            asm volatile("cp.async.cg.shared.global [%0], [%1], 16;" :: "r"(db), "l"(sb));
        }
        asm volatile("cp.async.commit_group;");
    };

    stage_load(0, 0);
    const int NK = K / 32;  // 8
    for (int kt = 0; kt < NK; kt++) {
        int st = kt & 1;
        asm volatile("cp.async.wait_group 0;");
        __syncthreads();
        if (kt + 1 < NK) stage_load(kt + 1, st ^ 1);

#pragma unroll
        for (int kc = 0; kc < 2; kc++) {
            uint32_t a[4][4];
#pragma unroll
            for (int mf = 0; mf < 4; mf++) {
                unsigned ad = (unsigned)__cvta_generic_to_shared(
                    &As[st][wm + mf * 16 + (lane & 15)][kc * 16 + (lane >> 4) * 8]);
                LDSM4(a[mf][0], a[mf][1], a[mf][2], a[mf][3], ad);
            }
            uint32_t bf[2][4];
#pragma unroll
            for (int p = 0; p < 2; p++) {
                int nrow = wn + p * 16 + (lane & 7) + ((lane >> 4) & 1) * 8;
                int kcol = kc * 16 + ((lane >> 3) & 1) * 8;
                unsigned bd = (unsigned)__cvta_generic_to_shared(&Bs[st][nrow][kcol]);
                LDSM4(bf[p][0], bf[p][1], bf[p][2], bf[p][3], bd);
            }
#pragma unroll
            for (int mf = 0; mf < 4; mf++)
#pragma unroll
                for (int nf = 0; nf < 4; nf++) {
                    uint32_t b0 = bf[nf >> 1][(nf & 1) * 2 + 0];
                    uint32_t b1 = bf[nf >> 1][(nf & 1) * 2 + 1];
                    asm volatile(
                        "mma.sync.aligned.m16n8k16.row.col.f32.f16.f16.f32 "
                        "{%0,%1,%2,%3}, {%4,%5,%6,%7}, {%8,%9}, {%0,%1,%2,%3};"
                        : "+f"(acc[mf][nf][0]), "+f"(acc[mf][nf][1]),
                          "+f"(acc[mf][nf][2]), "+f"(acc[mf][nf][3])
                        : "r"(a[mf][0]), "r"(a[mf][1]), "r"(a[mf][2]), "r"(a[mf][3]),
                          "r"(b0), "r"(b1));
                }
        }
    }

#pragma unroll
    for (int mf = 0; mf < 4; mf++)
#pragma unroll
        for (int nf = 0; nf < 4; nf++) {
            int r0 = m0 + wm + mf * 16 + (lane >> 2);
            int cx = n0 + wn + nf * 8 + (lane & 3) * 2;
            *(__half2*)&Ct[(size_t)r0 * NN + cx] =
                __floats2half2_rn(acc[mf][nf][0], acc[mf][nf][1]);
            *(__half2*)&Ct[(size_t)(r0 + 8) * NN + cx] =
                __floats2half2_rn(acc[mf][nf][2], acc[mf][nf][3]);
        }
}

// ---------------------------------------------------------------------------
// mLSTM recurrence. Same structure as sLSTM + bilinear term from g_t.
// ---------------------------------------------------------------------------
__global__ void __launch_bounds__(512) mlstm_kernel(const float* __restrict__ xg,
                                                    const float* __restrict__ Uw,
                                                    const float* __restrict__ Ub,
                                                    const __half* __restrict__ tbl,
                                                    const float* __restrict__ Bb,
                                                    float* __restrict__ out) {
    const int blk = blockIdx.x;
    const int b = blk >> 3, ci = blk & 7;
    const int tid = threadIdx.x;
    const int gl = tid >> 2;
    const int q  = tid & 3;
    const int type = gl >> 5;
    const int ul = gl & 31;
    const int row = type * HH + ci * 32 + ul;
    const int o_l = tid >> 4;         // 0..31 (bilinear o)
    const int kq  = tid & 15;         // 16-way split over k
    const int o_g = ci * 32 + o_l;

    __shared__ float h_s[HH];
    __shared__ float sg[128];
    __shared__ float sm_m[32];

    float4 u[16];
    const float4* Up = (const float4*)(Uw + (size_t)row * HH + q * 64);
#pragma unroll
    for (int i = 0; i < 16; i++) u[i] = Up[i];
    const float ubias = Ub[row];
    float c = 0.f;
    const float bb = (tid < 32) ? Bb[ci * 32 + tid] : 0.f;
    const float* xgb = xg + (size_t)b * TT * G4H;

    for (int t = 0; t < TT; t++) {
        __syncthreads();
        if (tid < HH) h_s[tid] = __ldcg(&g_hstate[t % 3][b][tid]);
        __syncthreads();

        // gate pre-activation
        float acc = (q == 0) ? (xgb[(size_t)t * G4H + row] + ubias) : 0.f;
        const float4* hp = (const float4*)(h_s + q * 64);
#pragma unroll
        for (int i = 0; i < 16; i++) {
            float4 hv = hp[i];
            acc += u[i].x * hv.x + u[i].y * hv.y + u[i].z * hv.z + u[i].w * hv.w;
        }
        acc += __shfl_down_sync(0xffffffffu, acc, 2, 4);
        acc += __shfl_down_sync(0xffffffffu, acc, 1, 4);
        if (q == 0) sg[gl] = acc;

        // bilinear: sum_k t[b,t,o_g,k] * h[k]
        float macc = 0.f;
        const __half2* tp = (const __half2*)(tbl + (((size_t)b * TT + t) * HH + o_g) * HH + kq * 16);
#pragma unroll
        for (int i = 0; i < 8; i++) {
            float2 tf = __half22float2(tp[i]);
            float2 hv = *(const float2*)&h_s[kq * 16 + 2 * i];
            macc += tf.x * hv.x + tf.y * hv.y;
        }
        macc += __shfl_down_sync(0xffffffffu, macc, 8, 16);
        macc += __shfl_down_sync(0xffffffffu, macc, 4, 16);
        macc += __shfl_down_sync(0xffffffffu, macc, 2, 16);
        macc += __shfl_down_sync(0xffffffffu, macc, 1, 16);
        if (kq == 0) sm_m[o_l] = macc;
        __syncthreads();

        if (tid < 32) {
            float iv = sg[tid], fv = sg[32 + tid], ov = sg[64 + tid], gv = sg[96 + tid];
            float m = tanhf(sm_m[tid] + bb);
            c = sigmoidf_(fv) * c + sigmoidf_(iv) * tanhf(gv) + SCALE_C * m;
            float h = sigmoidf_(ov) * tanhf(c);
            int ug = ci * 32 + tid;
            g_hstate[(t + 1) % 3][b][ug] = h;
            out[((size_t)b * TT + t) * HH + ug] = h;
            __threadfence();
        }
        __syncthreads();
        if (tid == 0) {
            atomicAdd(&g_cnt2[b], 1);
            while (atomicAdd(&g_cnt2[b], 0) < 8 * (t + 1)) {}
        }
        __syncthreads();
    }
}

// ---------------------------------------------------------------------------
// launch
// ---------------------------------------------------------------------------
extern "C" void kernel_launch(void* const* d_in, const int* in_sizes, int n_in,
                              void* d_out, int out_size) {
    const float* x     = (const float*)d_in[0];
    const float* W1w   = (const float*)d_in[1];
    const float* W1b   = (const float*)d_in[2];
    const float* U1w   = (const float*)d_in[3];
    const float* U1b   = (const float*)d_in[4];
    const float* alpha = (const float*)d_in[5];
    const float* W2w   = (const float*)d_in[6];
    const float* W2b   = (const float*)d_in[7];
    const float* U2w   = (const float*)d_in[8];
    const float* U2b   = (const float*)d_in[9];
    const float* Bw    = (const float*)d_in[10];
    const float* Bb    = (const float*)d_in[11];
    float* out = (float*)d_out;

    float  *xg1, *xg2, *h1;
    __half *h1h, *Bt, *tt;
    cudaGetSymbolAddress((void**)&xg1, g_xg1);
    cudaGetSymbolAddress((void**)&xg2, g_xg2);
    cudaGetSymbolAddress((void**)&h1,  g_h1);
    cudaGetSymbolAddress((void**)&h1h, g_h1h);
    cudaGetSymbolAddress((void**)&Bt,  g_Bt);
    cudaGetSymbolAddress((void**)&tt,  g_t);

    init_kernel<<<12, 1024>>>();

    // xg1 = x @ W1w^T + W1b   (M=8192, N=1024, K=512)
    sgemm_nt<<<dim3(8, 64), 256>>>(x, W1w, W1b, xg1, BB * TT, G4H, DD);

    // Bw transpose can overlap nothing (single stream) but is cheap
    transpose_Bw<<<dim3(8, 8, 256), dim3(32, 8)>>>(Bw, Bt);

    // sLSTM
    slstm_kernel<<<128, 512>>>(xg1, U1w, U1b, alpha, h1, h1h);

    // xg2 = h1 @ W2w^T + W2b  (M=8192, N=1024, K=256)
    sgemm_nt<<<dim3(8, 64), 256>>>(h1, W2w, W2b, xg2, BB * TT, G4H, HH);

    // t[b,t,o,k] = sum_d h1[b,t,d] * Bw[o,d,k]  (M=8192, N=65536, K=256)
    hgemm_kernel<<<dim3(512, 64), 256>>>(h1h, Bt, tt);

    zero_h0_kernel<<<4, 1024>>>();

    // mLSTM
    mlstm_kernel<<<128, 512>>>(xg2, U2w, U2b, tt, Bb, out);
}